// round 1
// baseline (speedup 1.0000x reference)
#include <cuda_runtime.h>
#include <cuda_bf16.h>
#include <math.h>

// Problem shape (fixed by the dataset)
#define B 8
#define S 2048
#define D 2048
#define E 8
#define EPS 1e-5f

#define S_CHUNK 64               // S / 32 chunks
#define D4 (D / 4)               // 512 float4 per row

// Scratch: xm accumulator (raw sums over S; divided by S in finalize)
__device__ float g_xm[B * D];

__global__ void zero_xm_kernel() {
    int i = blockIdx.x * blockDim.x + threadIdx.x;
    if (i < B * D) g_xm[i] = 0.0f;
}

// Column reduction over S: grid (D4/256, S/S_CHUNK, B), block 256.
__global__ void colsum_kernel(const float4* __restrict__ x4) {
    int d4 = blockIdx.x * blockDim.x + threadIdx.x;   // 0..511
    int b  = blockIdx.z;
    int s0 = blockIdx.y * S_CHUNK;
    const float4* p = x4 + ((size_t)b * S + s0) * D4 + d4;
    float4 acc = make_float4(0.f, 0.f, 0.f, 0.f);
#pragma unroll 8
    for (int i = 0; i < S_CHUNK; i++) {
        float4 v = p[(size_t)i * D4];
        acc.x += v.x; acc.y += v.y; acc.z += v.z; acc.w += v.w;
    }
    float* dst = g_xm + b * D + d4 * 4;
    atomicAdd(dst + 0, acc.x);
    atomicAdd(dst + 1, acc.y);
    atomicAdd(dst + 2, acc.z);
    atomicAdd(dst + 3, acc.w);
}

// One block, 256 threads (8 warps). Does everything small.
__global__ void finalize_kernel(const float* __restrict__ W,
                                const float* __restrict__ gain,
                                const float* __restrict__ init_std,
                                const float* __restrict__ noise,
                                const int*   __restrict__ topk_p,
                                float* __restrict__ out, int out_size) {
    int tid = threadIdx.x, warp = tid >> 5, lane = tid & 31;
    __shared__ float s_scale[E], s_mean[E];
    __shared__ float s_dot[B][E], s_xsum[B];

    // ---- per-expert W stats: warp e handles expert e ----
    {
        const float* w = W + warp * D;
        float s = 0.f, ss = 0.f;
        for (int i = lane; i < D; i += 32) {
            float v = w[i];
            s += v; ss += v * v;
        }
#pragma unroll
        for (int o = 16; o; o >>= 1) {
            s  += __shfl_xor_sync(0xFFFFFFFFu, s,  o);
            ss += __shfl_xor_sync(0xFFFFFFFFu, ss, o);
        }
        if (lane == 0) {
            float mean = s / (float)D;
            float var  = (ss - (float)D * mean * mean) / (float)(D - 1);
            float std  = sqrtf(fmaxf(var, 0.f)) + EPS;
            s_mean[warp]  = mean;
            s_scale[warp] = init_std[warp] / std * gain[warp];
        }
    }
    __syncthreads();

    // ---- dots: warp b computes xsum[b] and dot[b][e] for all e ----
    {
        int b = warp;
        const float* xb = g_xm + b * D;
        float xsum = 0.f;
        float dot[E];
#pragma unroll
        for (int e = 0; e < E; e++) dot[e] = 0.f;
        for (int i = lane; i < D; i += 32) {
            float xv = xb[i];
            xsum += xv;
#pragma unroll
            for (int e = 0; e < E; e++) dot[e] += xv * W[e * D + i];
        }
#pragma unroll
        for (int o = 16; o; o >>= 1) {
            xsum += __shfl_xor_sync(0xFFFFFFFFu, xsum, o);
#pragma unroll
            for (int e = 0; e < E; e++)
                dot[e] += __shfl_xor_sync(0xFFFFFFFFu, dot[e], o);
        }
        if (lane == 0) {
            s_xsum[b] = xsum;
#pragma unroll
            for (int e = 0; e < E; e++) s_dot[b][e] = dot[e];
        }
    }
    __syncthreads();

    // ---- per-batch softmax + top-k: thread b < B ----
    if (tid < B) {
        int b = tid;
        int k = *topk_p;
        if (k > E) k = E;
        const float invS = 1.0f / (float)S;
        float sc[E];
        float mx = -INFINITY;
#pragma unroll
        for (int e = 0; e < E; e++) {
            float v = s_scale[e] * (s_dot[b][e] - s_mean[e] * s_xsum[b]) * invS
                      + noise[b * E + e];
            sc[e] = v;
            mx = fmaxf(mx, v);
        }
        float denom = 0.f;
#pragma unroll
        for (int e = 0; e < E; e++) { sc[e] = expf(sc[e] - mx); denom += sc[e]; }
        float inv = 1.0f / denom;
#pragma unroll
        for (int e = 0; e < E; e++) sc[e] *= inv;  // gate_probs

        // combine tensor region [0, B*E)
        float comb[E];
#pragma unroll
        for (int e = 0; e < E; e++) comb[e] = 0.f;

        bool taken[E];
#pragma unroll
        for (int e = 0; e < E; e++) taken[e] = false;

        for (int kk = 0; kk < k; kk++) {
            int best = -1;
            float bv = -INFINITY;
            for (int e = 0; e < E; e++) {
                if (!taken[e] && sc[e] > bv) { bv = sc[e]; best = e; }
            }
            taken[best] = true;
            comb[best] = bv;
            // indices region [B*E, B*E + B*k), scores region [B*E + B*k, ...)
            int idx_off = B * E + b * k + kk;
            int scr_off = B * E + B * k + b * k + kk;
            if (idx_off < out_size) out[idx_off] = (float)best;
            if (scr_off < out_size) out[scr_off] = bv;
        }
#pragma unroll
        for (int e = 0; e < E; e++) {
            int o = b * E + e;
            if (o < out_size) out[o] = comb[e];
        }
    }
}

extern "C" void kernel_launch(void* const* d_in, const int* in_sizes, int n_in,
                              void* d_out, int out_size) {
    const float* x        = (const float*)d_in[0];
    const float* W        = (const float*)d_in[1];
    const float* gain     = (const float*)d_in[2];
    const float* init_std = (const float*)d_in[3];
    const float* noise    = (const float*)d_in[4];
    const int*   topk     = (const int*)d_in[5];
    float* out = (float*)d_out;

    zero_xm_kernel<<<(B * D + 255) / 256, 256>>>();

    dim3 grid(D4 / 256, S / S_CHUNK, B);
    colsum_kernel<<<grid, 256>>>((const float4*)x);

    finalize_kernel<<<1, 256>>>(W, gain, init_std, noise, topk, out, out_size);
}

// round 2
// speedup vs baseline: 1.7105x; 1.7105x over previous
#include <cuda_runtime.h>
#include <cuda_bf16.h>
#include <math.h>

#define B 8
#define S 2048
#define D 2048
#define E 8
#define EPS 1e-5f

#define D4 (D / 4)            // 512 float4 per row
#define S_CHUNK 64            // rows per CTA
#define GX 2                  // D4 / 256
#define GY (S / S_CHUNK)      // 32
#define NBLK (GX * GY * B)    // 512

// Scratch: [0,64) = dot_raw[b*E+e], [64,72) = xsum[b]. Zero-initialized;
// the finalizing block re-zeroes it each launch (graph-replay safe).
__device__ float g_acc[B * E + B];
__device__ unsigned int g_ticket;

__global__ void __launch_bounds__(256) router_kernel(
    const float4* __restrict__ x4,
    const float4* __restrict__ W4,
    const float*  __restrict__ gain,
    const float*  __restrict__ init_std,
    const float*  __restrict__ noise,
    const int*    __restrict__ topk_p,
    float* __restrict__ out, int out_size)
{
    const int tid  = threadIdx.x;
    const int warp = tid >> 5, lane = tid & 31;
    const int d4   = blockIdx.x * 256 + tid;      // 0..511
    const int b    = blockIdx.z;
    const int s0   = blockIdx.y * S_CHUNK;

    // ---- stream x: partial column sums over S_CHUNK rows ----
    const float4* p = x4 + ((size_t)b * S + s0) * D4 + d4;
    float4 acc = make_float4(0.f, 0.f, 0.f, 0.f);
#pragma unroll 8
    for (int i = 0; i < S_CHUNK; i++) {
        float4 v = p[(size_t)i * D4];
        acc.x += v.x; acc.y += v.y; acc.z += v.z; acc.w += v.w;
    }

    // ---- contract against W in-registers: 9 partials per thread ----
    float v9[9];
#pragma unroll
    for (int e = 0; e < E; e++) {
        float4 w = W4[e * D4 + d4];
        v9[e] = acc.x * w.x + acc.y * w.y + acc.z * w.z + acc.w * w.w;
    }
    v9[8] = acc.x + acc.y + acc.z + acc.w;        // xsum partial

    // ---- block reduce 9 values ----
    __shared__ float s_red[9][8];
#pragma unroll
    for (int o = 16; o; o >>= 1)
#pragma unroll
        for (int i = 0; i < 9; i++)
            v9[i] += __shfl_xor_sync(0xFFFFFFFFu, v9[i], o);
    if (lane == 0)
#pragma unroll
        for (int i = 0; i < 9; i++) s_red[i][warp] = v9[i];
    __syncthreads();
    if (tid < 9) {
        float s = 0.f;
#pragma unroll
        for (int w = 0; w < 8; w++) s += s_red[tid][w];
        atomicAdd(&g_acc[tid < 8 ? b * E + tid : 64 + b], s);
    }

    // ---- last-block ticket ----
    __threadfence();
    __shared__ bool is_last;
    if (tid == 0) {
        unsigned t = atomicAdd(&g_ticket, 1u);
        is_last = (t == NBLK - 1);
    }
    __syncthreads();
    if (!is_last) return;

    // ================= finalize (one block) =================
    __shared__ float s_dot[B * E], s_xsum[B], s_scale[E], s_mean[E];
    if (tid < B * E) s_dot[tid] = __ldcg(&g_acc[tid]);
    if (tid < B)     s_xsum[tid] = __ldcg(&g_acc[64 + tid]);

    // per-expert W stats: warp e -> expert e (float4 loads, 16 per lane)
    {
        const float4* wrow = W4 + warp * D4;
        float s = 0.f, ss = 0.f;
#pragma unroll 4
        for (int i = lane; i < D4; i += 32) {
            float4 w = wrow[i];
            s  += w.x + w.y + w.z + w.w;
            ss += w.x * w.x + w.y * w.y + w.z * w.z + w.w * w.w;
        }
#pragma unroll
        for (int o = 16; o; o >>= 1) {
            s  += __shfl_xor_sync(0xFFFFFFFFu, s,  o);
            ss += __shfl_xor_sync(0xFFFFFFFFu, ss, o);
        }
        if (lane == 0) {
            float mean = s / (float)D;
            float var  = (ss - (float)D * mean * mean) / (float)(D - 1);
            float std  = sqrtf(fmaxf(var, 0.f)) + EPS;
            s_mean[warp]  = mean;
            s_scale[warp] = init_std[warp] / std * gain[warp];
        }
    }
    __syncthreads();

    // per-batch softmax + top-k
    if (tid < B) {
        const int bb = tid;
        int k = *topk_p;
        if (k > E) k = E;
        const float invS = 1.0f / (float)S;
        float sc[E];
        float mx = -INFINITY;
#pragma unroll
        for (int e = 0; e < E; e++) {
            float v = s_scale[e] * (s_dot[bb * E + e] - s_mean[e] * s_xsum[bb]) * invS
                      + noise[bb * E + e];
            sc[e] = v;
            mx = fmaxf(mx, v);
        }
        float denom = 0.f;
#pragma unroll
        for (int e = 0; e < E; e++) { sc[e] = expf(sc[e] - mx); denom += sc[e]; }
        float inv = 1.0f / denom;
#pragma unroll
        for (int e = 0; e < E; e++) sc[e] *= inv;

        float comb[E];
        bool taken[E];
#pragma unroll
        for (int e = 0; e < E; e++) { comb[e] = 0.f; taken[e] = false; }

        for (int kk = 0; kk < k; kk++) {
            int best = -1; float bv = -INFINITY;
            for (int e = 0; e < E; e++)
                if (!taken[e] && sc[e] > bv) { bv = sc[e]; best = e; }
            taken[best] = true;
            comb[best] = bv;
            int idx_off = B * E + bb * k + kk;
            int scr_off = B * E + B * k + bb * k + kk;
            if (idx_off < out_size) out[idx_off] = (float)best;
            if (scr_off < out_size) out[scr_off] = bv;
        }
#pragma unroll
        for (int e = 0; e < E; e++) {
            int o = bb * E + e;
            if (o < out_size) out[o] = comb[e];
        }
    }
    __syncthreads();

    // reset scratch for the next graph replay
    if (tid < B * E + B) g_acc[tid] = 0.f;
    if (tid == 0) g_ticket = 0u;
}

extern "C" void kernel_launch(void* const* d_in, const int* in_sizes, int n_in,
                              void* d_out, int out_size) {
    const float* x        = (const float*)d_in[0];
    const float* W        = (const float*)d_in[1];
    const float* gain     = (const float*)d_in[2];
    const float* init_std = (const float*)d_in[3];
    const float* noise    = (const float*)d_in[4];
    const int*   topk     = (const int*)d_in[5];
    float* out = (float*)d_out;

    dim3 grid(GX, GY, B);
    router_kernel<<<grid, 256>>>((const float4*)x, (const float4*)W,
                                 gain, init_std, noise, topk, out, out_size);
}